// round 1
// baseline (speedup 1.0000x reference)
#include <cuda_runtime.h>
#include <math.h>

#define H 512
#define BB 32
#define SS 128
#define TT 512
#define NHEAD 8
#define DHD 64
#define NL 4
#define FF 2048
#define NOUT 102
#define NJ 50

// ---------------- scratch (static device globals; no allocation) ----------------
__device__ float g_m[BB * SS * H];                 //  8 MB
__device__ float g_mem[BB * TT * H];               // 33 MB
__device__ float g_x[BB * TT * H];                 // 33 MB
__device__ float g_h[BB * TT * H];                 // 33 MB
__device__ float g_qkv[BB * TT * 3 * H];           // 100 MB
__device__ float g_scores[BB * NHEAD * TT * TT];   // 268 MB
__device__ float g_att[BB * TT * H];               // 33 MB
__device__ float g_ff[BB * TT * FF];               // 134 MB
__device__ float g_head[BB * TT * NOUT];           // 6.7 MB
__device__ float g_pe[TT * H];                     // 1 MB
__device__ float g_convT[4 * H * H];               // 4 MB

__constant__ int PAR[NJ] = {
    -1, 0, 1, 2, 3, 1, 5, 6, 1,
    4, 9, 10, 11,  4, 13, 14, 15,  4, 17, 18, 19,  4, 21, 22, 23,  4, 25, 26, 27,
    7, 29, 30, 31, 7, 33, 34, 35,  7, 37, 38, 39,  7, 41, 42, 43,  7, 45, 46, 47,
    8
};

// ---------------- epilogue modes ----------------
#define EPI_NONE 0
#define EPI_SCALE 1
#define EPI_BIAS 2
#define EPI_BIAS_RES 3
#define EPI_BIAS_GELU 4
#define EPI_CONV 5

// ---------------- generic tiled GEMM ----------------
// C[r,c] = sum_k A[r,k] * (TRANSB ? B[c,k] : B[k,c])     (per batch z)
// batch offsets: X += b*sXb + h*sXh, where b=z/nh, h=z%nh
constexpr int BM = 128, BN = 128, BK = 16;

template <bool TRANSB, int EPI>
__global__ void __launch_bounds__(256, 2) gemm_k(
    const float* __restrict__ A, const float* __restrict__ Bm,
    const float* __restrict__ bias, const float* __restrict__ resid,
    float* __restrict__ C,
    int M, int N, int K, int lda, int ldb, int ldc,
    long sAb, long sAh, long sBb, long sBh, long sCb, long sCh,
    int nh, float scale, int aux)
{
    __shared__ float sA[BK][BM + 4];
    __shared__ float sB[BK][BN + 4];

    int z = blockIdx.z;
    int bb = z / nh, hh = z - bb * nh;
    A += (long)bb * sAb + (long)hh * sAh;
    Bm += (long)bb * sBb + (long)hh * sBh;
    const long coff = (long)bb * sCb + (long)hh * sCh;

    const int row0 = blockIdx.y * BM;
    const int col0 = blockIdx.x * BN;
    const int tid = threadIdx.x;
    const int tr = tid >> 4;   // 0..15
    const int tc = tid & 15;   // 0..15

    float acc[8][8];
#pragma unroll
    for (int i = 0; i < 8; i++)
#pragma unroll
        for (int j = 0; j < 8; j++) acc[i][j] = 0.f;

    for (int k0 = 0; k0 < K; k0 += BK) {
        // A tile: BM x BK
#pragma unroll
        for (int l = 0; l < 8; l++) {
            int e = l * 256 + tid;
            int r = e >> 4, c = e & 15;
            int gr = row0 + r, gc = k0 + c;
            sA[c][r] = (gr < M && gc < K) ? A[(long)gr * lda + gc] : 0.f;
        }
        if (TRANSB) {
#pragma unroll
            for (int l = 0; l < 8; l++) {
                int e = l * 256 + tid;
                int n = e >> 4, c = e & 15;
                int gn = col0 + n, gc = k0 + c;
                sB[c][n] = (gn < N && gc < K) ? Bm[(long)gn * ldb + gc] : 0.f;
            }
        } else {
#pragma unroll
            for (int l = 0; l < 8; l++) {
                int e = l * 256 + tid;
                int r = e >> 7, c = e & 127;
                int gk = k0 + r, gn = col0 + c;
                sB[r][c] = (gk < K && gn < N) ? Bm[(long)gk * ldb + gn] : 0.f;
            }
        }
        __syncthreads();
#pragma unroll
        for (int kk = 0; kk < BK; kk++) {
            float a0[8], b0[8];
#pragma unroll
            for (int i = 0; i < 8; i++) a0[i] = sA[kk][tr * 8 + i];
#pragma unroll
            for (int j = 0; j < 8; j++) b0[j] = sB[kk][tc * 8 + j];
#pragma unroll
            for (int i = 0; i < 8; i++)
#pragma unroll
                for (int j = 0; j < 8; j++) acc[i][j] = fmaf(a0[i], b0[j], acc[i][j]);
        }
        __syncthreads();
    }

#pragma unroll
    for (int i = 0; i < 8; i++) {
        int r = row0 + tr * 8 + i;
        if (r >= M) continue;
#pragma unroll
        for (int j = 0; j < 8; j++) {
            int c = col0 + tc * 8 + j;
            if (c >= N) continue;
            float v = acc[i][j];
            if (EPI == EPI_SCALE) v *= scale;
            if (EPI == EPI_BIAS || EPI == EPI_BIAS_RES || EPI == EPI_BIAS_GELU || EPI == EPI_CONV)
                v += bias[c];
            if (EPI == EPI_BIAS_GELU)
                v = 0.5f * v * (1.f + erff(v * 0.70710678118654752f));
            if (EPI == EPI_CONV) {
                // input row r = b*128 + s ; output row = b*512 + s*4 + aux ; add pe
                int b_ = r >> 7;
                int s_ = r & 127;
                int t_ = s_ * 4 + aux;
                C[((long)b_ * TT + t_) * ldc + c] = v + resid[t_ * H + c];
            } else {
                long idx = coff + (long)r * ldc + c;
                if (EPI == EPI_BIAS_RES) v += resid[idx];
                C[idx] = v;
            }
        }
    }
}

// ---------------- LayerNorm (one block per row of 512) ----------------
__global__ void ln_k(const float* __restrict__ x, const float* __restrict__ g,
                     const float* __restrict__ b, float* __restrict__ o)
{
    long row = blockIdx.x;
    int t = threadIdx.x;  // 128
    float4 v = ((const float4*)(x + row * H))[t];
    float s = v.x + v.y + v.z + v.w;
    float ss = v.x * v.x + v.y * v.y + v.z * v.z + v.w * v.w;
#pragma unroll
    for (int off = 16; off; off >>= 1) {
        s += __shfl_xor_sync(0xffffffffu, s, off);
        ss += __shfl_xor_sync(0xffffffffu, ss, off);
    }
    __shared__ float sm0[4], sm1[4];
    int w = t >> 5;
    if ((t & 31) == 0) { sm0[w] = s; sm1[w] = ss; }
    __syncthreads();
    s = sm0[0] + sm0[1] + sm0[2] + sm0[3];
    ss = sm1[0] + sm1[1] + sm1[2] + sm1[3];
    float mean = s * (1.f / H);
    float var = ss * (1.f / H) - mean * mean;
    float rstd = rsqrtf(var + 1e-5f);
    float4 gg = ((const float4*)g)[t];
    float4 bb4 = ((const float4*)b)[t];
    float4 out;
    out.x = (v.x - mean) * rstd * gg.x + bb4.x;
    out.y = (v.y - mean) * rstd * gg.y + bb4.y;
    out.z = (v.z - mean) * rstd * gg.z + bb4.z;
    out.w = (v.w - mean) * rstd * gg.w + bb4.w;
    ((float4*)(o + row * H))[t] = out;
}

// ---------------- softmax over rows of 512 ----------------
__global__ void softmax_k(float* __restrict__ sc)
{
    long row = blockIdx.x;
    int t = threadIdx.x;  // 128
    float4* p = (float4*)(sc + row * 512);
    float4 v = p[t];
    float mx = fmaxf(fmaxf(v.x, v.y), fmaxf(v.z, v.w));
#pragma unroll
    for (int off = 16; off; off >>= 1) mx = fmaxf(mx, __shfl_xor_sync(0xffffffffu, mx, off));
    __shared__ float sm0[4], sm1[4];
    int w = t >> 5;
    if ((t & 31) == 0) sm0[w] = mx;
    __syncthreads();
    mx = fmaxf(fmaxf(sm0[0], sm0[1]), fmaxf(sm0[2], sm0[3]));
    v.x = expf(v.x - mx); v.y = expf(v.y - mx);
    v.z = expf(v.z - mx); v.w = expf(v.w - mx);
    float s = v.x + v.y + v.z + v.w;
#pragma unroll
    for (int off = 16; off; off >>= 1) s += __shfl_xor_sync(0xffffffffu, s, off);
    if ((t & 31) == 0) sm1[w] = s;
    __syncthreads();
    s = sm1[0] + sm1[1] + sm1[2] + sm1[3];
    float inv = 1.f / s;
    v.x *= inv; v.y *= inv; v.z *= inv; v.w *= inv;
    p[t] = v;
}

// ---------------- positional encoding ----------------
__global__ void pe_k(float* __restrict__ pe)
{
    int t = blockIdx.x;    // 0..511
    int i = threadIdx.x;   // 0..255
    float div = expf(-(float)(2 * i) * (logf(10000.f) / (float)H));
    float a = (float)t * div;
    pe[t * H + 2 * i] = sinf(a);
    pe[t * H + 2 * i + 1] = cosf(a);
}

// ---------------- conv weight transpose: convT[k][d][c] = conv_w[c][d][k] ----------------
__global__ void convT_k(const float* __restrict__ w, float* __restrict__ o)
{
    int idx = blockIdx.x * blockDim.x + threadIdx.x;
    if (idx >= 4 * H * H) return;
    int k = idx / (H * H);
    int d = (idx / H) % H;
    int c = idx % H;
    o[idx] = w[c * H * 4 + d * 4 + k];
}

// ---------------- x init: x = query_emb + pe ----------------
__global__ void xinit_k(const float* __restrict__ qe, const float* __restrict__ pe,
                        float* __restrict__ x)
{
    long i = blockIdx.x * (long)blockDim.x + threadIdx.x;
    if (i >= (long)BB * TT * H) return;
    int td = (int)(i % (TT * H));
    x[i] = qe[td] + pe[td];
}

// ---------------- forward kinematics head ----------------
__global__ void kin_k(const float* __restrict__ ho, float* __restrict__ out)
{
    int row = blockIdx.x * blockDim.x + threadIdx.x;
    if (row >= BB * TT) return;
    const float* r = ho + (long)row * NOUT;
    float* o = out + (long)row * (3 * NJ);
    float gx[NJ], px[NJ], py[NJ];
    gx[0] = 0.f;
    px[0] = r[100];
    py[0] = r[101];
    o[0] = px[0]; o[1] = py[0]; o[2] = 1.f;
    for (int j = 1; j < NJ; j++) {
        int pa = PAR[j];
        float gg = gx[pa] + r[j];
        gx[j] = gg;
        float s = r[50 + j];
        float sn, cs;
        sincosf(gg, &sn, &cs);
        px[j] = px[pa] + cs * s;
        py[j] = py[pa] + sn * s;
        o[j * 3 + 0] = px[j];
        o[j * 3 + 1] = py[j];
        o[j * 3 + 2] = 1.f;
    }
}

// ---------------- launcher ----------------
static inline dim3 gg(int M, int N, int bz = 1)
{
    return dim3((N + BN - 1) / BN, (M + BM - 1) / BM, bz);
}

#define Z6 0L, 0L, 0L, 0L, 0L, 0L

extern "C" void kernel_launch(void* const* d_in, const int* in_sizes, int n_in,
                              void* d_out, int out_size)
{
    const float* memory   = (const float*)d_in[0];
    const float* in_w     = (const float*)d_in[1];
    const float* in_b     = (const float*)d_in[2];
    const float* conv_w   = (const float*)d_in[3];
    const float* conv_b   = (const float*)d_in[4];
    const float* qemb     = (const float*)d_in[5];
    const float* sa_in_w  = (const float*)d_in[6];
    const float* sa_in_b  = (const float*)d_in[7];
    const float* sa_out_w = (const float*)d_in[8];
    const float* sa_out_b = (const float*)d_in[9];
    const float* ca_in_w  = (const float*)d_in[10];
    const float* ca_in_b  = (const float*)d_in[11];
    const float* ca_out_w = (const float*)d_in[12];
    const float* ca_out_b = (const float*)d_in[13];
    const float* ln1_g    = (const float*)d_in[14];
    const float* ln1_b    = (const float*)d_in[15];
    const float* ln2_g    = (const float*)d_in[16];
    const float* ln2_b    = (const float*)d_in[17];
    const float* ln3_g    = (const float*)d_in[18];
    const float* ln3_b    = (const float*)d_in[19];
    const float* ff1_w    = (const float*)d_in[20];
    const float* ff1_b    = (const float*)d_in[21];
    const float* ff2_w    = (const float*)d_in[22];
    const float* ff2_b    = (const float*)d_in[23];
    const float* out_w    = (const float*)d_in[24];
    const float* out_b    = (const float*)d_in[25];

    float *m_, *mem_, *x_, *h_, *qkv_, *sc_, *att_, *ff_, *ho_, *pe_, *cT_;
    cudaGetSymbolAddress((void**)&m_,   g_m);
    cudaGetSymbolAddress((void**)&mem_, g_mem);
    cudaGetSymbolAddress((void**)&x_,   g_x);
    cudaGetSymbolAddress((void**)&h_,   g_h);
    cudaGetSymbolAddress((void**)&qkv_, g_qkv);
    cudaGetSymbolAddress((void**)&sc_,  g_scores);
    cudaGetSymbolAddress((void**)&att_, g_att);
    cudaGetSymbolAddress((void**)&ff_,  g_ff);
    cudaGetSymbolAddress((void**)&ho_,  g_head);
    cudaGetSymbolAddress((void**)&pe_,  g_pe);
    cudaGetSymbolAddress((void**)&cT_,  g_convT);

    // prep
    pe_k<<<TT, 256>>>(pe_);
    convT_k<<<(4 * H * H + 255) / 256, 256>>>(conv_w, cT_);

    // m = memory @ in_w^T + in_b   (4096 x 512 x 512)
    gemm_k<true, EPI_BIAS><<<gg(BB * SS, H), 256>>>(
        memory, in_w, in_b, nullptr, m_,
        BB * SS, H, H, H, H, H, Z6, 1, 1.f, 0);

    // conv upsample: mem[b, s*4+k, :] = m[b,s,:] @ convT[k]^T + conv_b + pe
    for (int k = 0; k < 4; k++) {
        gemm_k<true, EPI_CONV><<<gg(BB * SS, H), 256>>>(
            m_, cT_ + (long)k * H * H, conv_b, pe_, mem_,
            BB * SS, H, H, H, H, H, Z6, 1, 1.f, k);
    }

    // x = query_emb + pe
    xinit_k<<<(BB * TT * H + 255) / 256, 256>>>(qemb, pe_, x_);

    const long sQb = (long)TT * 3 * H;   // per-batch stride into qkv rows
    const long sScb = (long)NHEAD * TT * TT;
    const long sSch = (long)TT * TT;

    for (int l = 0; l < NL; l++) {
        // ======== self-attention ========
        ln_k<<<BB * TT, 128>>>(x_, ln1_g + l * H, ln1_b + l * H, h_);
        gemm_k<true, EPI_BIAS><<<gg(BB * TT, 3 * H), 256>>>(
            h_, sa_in_w + (long)l * 3 * H * H, sa_in_b + (long)l * 3 * H, nullptr, qkv_,
            BB * TT, 3 * H, H, H, H, 3 * H, Z6, 1, 1.f, 0);
        // scores = q @ k^T * 1/8     (batched over 256 = B*NH)
        gemm_k<true, EPI_SCALE><<<dim3(4, 4, BB * NHEAD), 256>>>(
            qkv_, qkv_ + H, nullptr, nullptr, sc_,
            TT, TT, DHD, 3 * H, 3 * H, TT,
            sQb, (long)DHD, sQb, (long)DHD, sScb, sSch,
            NHEAD, 0.125f, 0);
        softmax_k<<<BB * NHEAD * TT, 128>>>(sc_);
        // att = scores @ v  -> (B*T, 512) with head remap via strides
        gemm_k<false, EPI_NONE><<<dim3(1, 4, BB * NHEAD), 256>>>(
            sc_, qkv_ + 2 * H, nullptr, nullptr, att_,
            TT, DHD, TT, TT, 3 * H, H,
            sScb, sSch, sQb, (long)DHD, (long)TT * H, (long)DHD,
            NHEAD, 1.f, 0);
        // x += att @ out_w^T + out_b
        gemm_k<true, EPI_BIAS_RES><<<gg(BB * TT, H), 256>>>(
            att_, sa_out_w + (long)l * H * H, sa_out_b + (long)l * H, x_, x_,
            BB * TT, H, H, H, H, H, Z6, 1, 1.f, 0);

        // ======== cross-attention ========
        ln_k<<<BB * TT, 128>>>(x_, ln2_g + l * H, ln2_b + l * H, h_);
        // q from h
        gemm_k<true, EPI_BIAS><<<gg(BB * TT, H), 256>>>(
            h_, ca_in_w + (long)l * 3 * H * H, ca_in_b + (long)l * 3 * H, nullptr, qkv_,
            BB * TT, H, H, H, H, 3 * H, Z6, 1, 1.f, 0);
        // k,v from mem
        gemm_k<true, EPI_BIAS><<<gg(BB * TT, 2 * H), 256>>>(
            mem_, ca_in_w + (long)l * 3 * H * H + (long)H * H,
            ca_in_b + (long)l * 3 * H + H, nullptr, qkv_ + H,
            BB * TT, 2 * H, H, H, H, 3 * H, Z6, 1, 1.f, 0);
        gemm_k<true, EPI_SCALE><<<dim3(4, 4, BB * NHEAD), 256>>>(
            qkv_, qkv_ + H, nullptr, nullptr, sc_,
            TT, TT, DHD, 3 * H, 3 * H, TT,
            sQb, (long)DHD, sQb, (long)DHD, sScb, sSch,
            NHEAD, 0.125f, 0);
        softmax_k<<<BB * NHEAD * TT, 128>>>(sc_);
        gemm_k<false, EPI_NONE><<<dim3(1, 4, BB * NHEAD), 256>>>(
            sc_, qkv_ + 2 * H, nullptr, nullptr, att_,
            TT, DHD, TT, TT, 3 * H, H,
            sScb, sSch, sQb, (long)DHD, (long)TT * H, (long)DHD,
            NHEAD, 1.f, 0);
        gemm_k<true, EPI_BIAS_RES><<<gg(BB * TT, H), 256>>>(
            att_, ca_out_w + (long)l * H * H, ca_out_b + (long)l * H, x_, x_,
            BB * TT, H, H, H, H, H, Z6, 1, 1.f, 0);

        // ======== FFN ========
        ln_k<<<BB * TT, 128>>>(x_, ln3_g + l * H, ln3_b + l * H, h_);
        gemm_k<true, EPI_BIAS_GELU><<<gg(BB * TT, FF), 256>>>(
            h_, ff1_w + (long)l * FF * H, ff1_b + (long)l * FF, nullptr, ff_,
            BB * TT, FF, H, H, H, FF, Z6, 1, 1.f, 0);
        gemm_k<true, EPI_BIAS_RES><<<gg(BB * TT, H), 256>>>(
            ff_, ff2_w + (long)l * H * FF, ff2_b + (long)l * H, x_, x_,
            BB * TT, H, FF, FF, FF, H, Z6, 1, 1.f, 0);
    }

    // head: (B*T, 102)
    gemm_k<true, EPI_BIAS><<<gg(BB * TT, NOUT), 256>>>(
        x_, out_w, out_b, nullptr, ho_,
        BB * TT, NOUT, H, H, H, NOUT, Z6, 1, 1.f, 0);

    // kinematics -> d_out (B*T, 150)
    kin_k<<<(BB * TT + 255) / 256, 256>>>(ho_, (float*)d_out);
}

// round 2
// speedup vs baseline: 1.4279x; 1.4279x over previous
#include <cuda_runtime.h>
#include <math.h>

#define H 512
#define BB 32
#define SS 128
#define TT 512
#define NHEAD 8
#define DHD 64
#define NL 4
#define FF 2048
#define NOUT 102
#define NJ 50

// ---------------- scratch (static device globals; no allocation) ----------------
__device__ float g_m[BB * SS * H];
__device__ float g_mem[BB * TT * H];
__device__ float g_x[BB * TT * H];
__device__ float g_h[BB * TT * H];
__device__ float g_qkv[BB * TT * 3 * H];
__device__ float g_scores[BB * NHEAD * TT * TT];
__device__ float g_att[BB * TT * H];
__device__ float g_ff[BB * TT * FF];
__device__ float g_head[BB * TT * NOUT];
__device__ float g_pe[TT * H];
__device__ float g_convT[4 * H * H];

__constant__ int PAR[NJ] = {
    -1, 0, 1, 2, 3, 1, 5, 6, 1,
    4, 9, 10, 11,  4, 13, 14, 15,  4, 17, 18, 19,  4, 21, 22, 23,  4, 25, 26, 27,
    7, 29, 30, 31, 7, 33, 34, 35,  7, 37, 38, 39,  7, 41, 42, 43,  7, 45, 46, 47,
    8
};

#define EPI_NONE 0
#define EPI_SCALE 1
#define EPI_BIAS 2
#define EPI_BIAS_RES 3
#define EPI_BIAS_GELU 4
#define EPI_CONV 5

// ---------------- pipelined tiled GEMM ----------------
// C[r,c] = sum_k A[r,k] * (TRANSB ? B[c,k] : B[k,c])  per batch z
// Requirements: K % 16 == 0; M % 128 == 0; float4-aligned A/B rows.
// Double-buffered smem, register prefetch, float4 LDG + LDS.128 fragments.
template <bool TRANSB, int EPI, int BN_>
__global__ void __launch_bounds__(256, 2) gemm2(
    const float* __restrict__ A, const float* __restrict__ Bm,
    const float* __restrict__ bias, const float* __restrict__ resid,
    float* __restrict__ C,
    int M, int N, int K, int lda, int ldb, int ldc,
    long sAb, long sAh, long sBb, long sBh, long sCb, long sCh,
    int nh, float scale)
{
    constexpr int BM = 128, BK = 16;
    constexpr int TN = BN_ / 16;                 // 8 or 4 cols per thread
    constexpr int LDAS = BM + 4, LDBS = BN_ + 4;
    constexpr int NBL = TRANSB ? (BN_ * BK / 4) / 256 : (BK * BN_ / 4) / 256;

    __shared__ float sA[2][BK][LDAS];
    __shared__ float sB[2][BK][LDBS];

    const int z = blockIdx.z;
    const int bb = z / nh, hh = z - bb * nh;
    A += (long)bb * sAb + (long)hh * sAh;
    Bm += (long)bb * sBb + (long)hh * sBh;
    const long coff = (long)bb * sCb + (long)hh * sCh;

    const int row0 = blockIdx.y * BM;
    const int col0 = blockIdx.x * BN_;
    const int tid = threadIdx.x;
    const int tr = tid >> 4;     // 0..15
    const int tc = tid & 15;     // 0..15

    float4 rA[2];
    float4 rB[NBL];

    float acc[8][TN];
#pragma unroll
    for (int i = 0; i < 8; i++)
#pragma unroll
        for (int j = 0; j < TN; j++) acc[i][j] = 0.f;

    // ---- tile loaders (global -> regs) ----
    auto ldg = [&](int k0) {
#pragma unroll
        for (int l = 0; l < 2; l++) {
            int idx = l * 256 + tid;
            int r = idx >> 2;              // 0..127
            int kq = (idx & 3) * 4;        // 0,4,8,12
            int gr = row0 + r;
            rA[l] = (gr < M) ? *(const float4*)(A + (long)gr * lda + k0 + kq)
                             : make_float4(0.f, 0.f, 0.f, 0.f);
        }
        if (TRANSB) {
#pragma unroll
            for (int l = 0; l < NBL; l++) {
                int idx = l * 256 + tid;
                int n = idx >> 2;          // 0..BN_-1
                int kq = (idx & 3) * 4;
                int gn = col0 + n;
                rB[l] = (gn < N) ? *(const float4*)(Bm + (long)gn * ldb + k0 + kq)
                                 : make_float4(0.f, 0.f, 0.f, 0.f);
            }
        } else {
            // BK x BN_ tile, n contiguous. NBL = BN_/64 per 256 threads.
#pragma unroll
            for (int l = 0; l < NBL; l++) {
                int idx = l * 256 + tid;
                int kk = idx / (BN_ / 4);
                int nq = (idx % (BN_ / 4)) * 4;
                int gn = col0 + nq;
                rB[l] = (gn < N) ? *(const float4*)(Bm + (long)(k0 + kk) * ldb + gn)
                                 : make_float4(0.f, 0.f, 0.f, 0.f);
            }
        }
    };

    // ---- regs -> smem stage st ----
    auto sts = [&](int st) {
#pragma unroll
        for (int l = 0; l < 2; l++) {
            int idx = l * 256 + tid;
            int r = idx >> 2;
            int kq = (idx & 3) * 4;
            sA[st][kq + 0][r] = rA[l].x;
            sA[st][kq + 1][r] = rA[l].y;
            sA[st][kq + 2][r] = rA[l].z;
            sA[st][kq + 3][r] = rA[l].w;
        }
        if (TRANSB) {
#pragma unroll
            for (int l = 0; l < NBL; l++) {
                int idx = l * 256 + tid;
                int n = idx >> 2;
                int kq = (idx & 3) * 4;
                sB[st][kq + 0][n] = rB[l].x;
                sB[st][kq + 1][n] = rB[l].y;
                sB[st][kq + 2][n] = rB[l].z;
                sB[st][kq + 3][n] = rB[l].w;
            }
        } else {
#pragma unroll
            for (int l = 0; l < NBL; l++) {
                int idx = l * 256 + tid;
                int kk = idx / (BN_ / 4);
                int nq = (idx % (BN_ / 4)) * 4;
                *(float4*)&sB[st][kk][nq] = rB[l];
            }
        }
    };

    auto compute = [&](int st) {
#pragma unroll
        for (int kk = 0; kk < BK; kk++) {
            float a[8], b[TN];
            *(float4*)&a[0] = *(const float4*)&sA[st][kk][tr * 8];
            *(float4*)&a[4] = *(const float4*)&sA[st][kk][tr * 8 + 4];
#pragma unroll
            for (int jq = 0; jq < TN / 4; jq++)
                *(float4*)&b[jq * 4] = *(const float4*)&sB[st][kk][tc * TN + jq * 4];
#pragma unroll
            for (int i = 0; i < 8; i++)
#pragma unroll
                for (int j = 0; j < TN; j++)
                    acc[i][j] = fmaf(a[i], b[j], acc[i][j]);
        }
    };

    const int nt = K / BK;
    ldg(0);
    sts(0);
    __syncthreads();
    for (int t = 1; t < nt; t++) {
        ldg(t * BK);          // prefetch next tile into regs
        compute((t - 1) & 1); // compute current tile (hides LDG latency)
        sts(t & 1);
        __syncthreads();
    }
    compute((nt - 1) & 1);

    // ---- epilogue ----
#pragma unroll
    for (int i = 0; i < 8; i++) {
        int r = row0 + tr * 8 + i;
        if (r >= M) continue;
#pragma unroll
        for (int j = 0; j < TN; j++) {
            int c = col0 + tc * TN + j;
            if (c >= N) continue;
            float v = acc[i][j];
            if (EPI == EPI_SCALE) v *= scale;
            if (EPI == EPI_BIAS || EPI == EPI_BIAS_RES || EPI == EPI_BIAS_GELU || EPI == EPI_CONV)
                v += bias[c];
            if (EPI == EPI_BIAS_GELU)
                v = 0.5f * v * (1.f + erff(v * 0.70710678118654752f));
            if (EPI == EPI_CONV) {
                // r = b*128 + s ; out row = b*512 + s*4 + hh ; add pe
                int b_ = r >> 7;
                int s_ = r & 127;
                int t_ = s_ * 4 + hh;
                C[((long)b_ * TT + t_) * ldc + c] = v + resid[t_ * H + c];
            } else {
                long idx = coff + (long)r * ldc + c;
                if (EPI == EPI_BIAS_RES) v += resid[idx];
                C[idx] = v;
            }
        }
    }
}

// ---------------- LayerNorm (one block per row of 512) ----------------
__global__ void ln_k(const float* __restrict__ x, const float* __restrict__ g,
                     const float* __restrict__ b, float* __restrict__ o)
{
    long row = blockIdx.x;
    int t = threadIdx.x;  // 128
    float4 v = ((const float4*)(x + row * H))[t];
    float s = v.x + v.y + v.z + v.w;
    float ss = v.x * v.x + v.y * v.y + v.z * v.z + v.w * v.w;
#pragma unroll
    for (int off = 16; off; off >>= 1) {
        s += __shfl_xor_sync(0xffffffffu, s, off);
        ss += __shfl_xor_sync(0xffffffffu, ss, off);
    }
    __shared__ float sm0[4], sm1[4];
    int w = t >> 5;
    if ((t & 31) == 0) { sm0[w] = s; sm1[w] = ss; }
    __syncthreads();
    s = sm0[0] + sm0[1] + sm0[2] + sm0[3];
    ss = sm1[0] + sm1[1] + sm1[2] + sm1[3];
    float mean = s * (1.f / H);
    float var = ss * (1.f / H) - mean * mean;
    float rstd = rsqrtf(var + 1e-5f);
    float4 gg = ((const float4*)g)[t];
    float4 bb4 = ((const float4*)b)[t];
    float4 out;
    out.x = (v.x - mean) * rstd * gg.x + bb4.x;
    out.y = (v.y - mean) * rstd * gg.y + bb4.y;
    out.z = (v.z - mean) * rstd * gg.z + bb4.z;
    out.w = (v.w - mean) * rstd * gg.w + bb4.w;
    ((float4*)(o + row * H))[t] = out;
}

// ---------------- softmax over rows of 512 ----------------
__global__ void softmax_k(float* __restrict__ sc)
{
    long row = blockIdx.x;
    int t = threadIdx.x;  // 128
    float4* p = (float4*)(sc + row * 512);
    float4 v = p[t];
    float mx = fmaxf(fmaxf(v.x, v.y), fmaxf(v.z, v.w));
#pragma unroll
    for (int off = 16; off; off >>= 1) mx = fmaxf(mx, __shfl_xor_sync(0xffffffffu, mx, off));
    __shared__ float sm0[4], sm1[4];
    int w = t >> 5;
    if ((t & 31) == 0) sm0[w] = mx;
    __syncthreads();
    mx = fmaxf(fmaxf(sm0[0], sm0[1]), fmaxf(sm0[2], sm0[3]));
    v.x = expf(v.x - mx); v.y = expf(v.y - mx);
    v.z = expf(v.z - mx); v.w = expf(v.w - mx);
    float s = v.x + v.y + v.z + v.w;
#pragma unroll
    for (int off = 16; off; off >>= 1) s += __shfl_xor_sync(0xffffffffu, s, off);
    if ((t & 31) == 0) sm1[w] = s;
    __syncthreads();
    s = sm1[0] + sm1[1] + sm1[2] + sm1[3];
    float inv = 1.f / s;
    v.x *= inv; v.y *= inv; v.z *= inv; v.w *= inv;
    p[t] = v;
}

// ---------------- positional encoding ----------------
__global__ void pe_k(float* __restrict__ pe)
{
    int t = blockIdx.x;
    int i = threadIdx.x;
    float div = expf(-(float)(2 * i) * (logf(10000.f) / (float)H));
    float a = (float)t * div;
    pe[t * H + 2 * i] = sinf(a);
    pe[t * H + 2 * i + 1] = cosf(a);
}

// ---------------- conv weight transpose ----------------
__global__ void convT_k(const float* __restrict__ w, float* __restrict__ o)
{
    int idx = blockIdx.x * blockDim.x + threadIdx.x;
    if (idx >= 4 * H * H) return;
    int k = idx / (H * H);
    int d = (idx / H) % H;
    int c = idx % H;
    o[idx] = w[c * H * 4 + d * 4 + k];
}

// ---------------- x init ----------------
__global__ void xinit_k(const float* __restrict__ qe, const float* __restrict__ pe,
                        float* __restrict__ x)
{
    long i = blockIdx.x * (long)blockDim.x + threadIdx.x;
    if (i >= (long)BB * TT * H) return;
    int td = (int)(i % (TT * H));
    x[i] = qe[td] + pe[td];
}

// ---------------- forward kinematics head ----------------
__global__ void kin_k(const float* __restrict__ ho, float* __restrict__ out)
{
    int row = blockIdx.x * blockDim.x + threadIdx.x;
    if (row >= BB * TT) return;
    const float* r = ho + (long)row * NOUT;
    float* o = out + (long)row * (3 * NJ);
    float gx[NJ], px[NJ], py[NJ];
    gx[0] = 0.f;
    px[0] = r[100];
    py[0] = r[101];
    o[0] = px[0]; o[1] = py[0]; o[2] = 1.f;
    for (int j = 1; j < NJ; j++) {
        int pa = PAR[j];
        float gg = gx[pa] + r[j];
        gx[j] = gg;
        float s = r[50 + j];
        float sn, cs;
        sincosf(gg, &sn, &cs);
        px[j] = px[pa] + cs * s;
        py[j] = py[pa] + sn * s;
        o[j * 3 + 0] = px[j];
        o[j * 3 + 1] = py[j];
        o[j * 3 + 2] = 1.f;
    }
}

// ---------------- launcher ----------------
static inline dim3 gg128(int M, int N, int bz = 1)
{
    return dim3((N + 127) / 128, (M + 127) / 128, bz);
}

#define Z6 0L, 0L, 0L, 0L, 0L, 0L

extern "C" void kernel_launch(void* const* d_in, const int* in_sizes, int n_in,
                              void* d_out, int out_size)
{
    const float* memory   = (const float*)d_in[0];
    const float* in_w     = (const float*)d_in[1];
    const float* in_b     = (const float*)d_in[2];
    const float* conv_w   = (const float*)d_in[3];
    const float* conv_b   = (const float*)d_in[4];
    const float* qemb     = (const float*)d_in[5];
    const float* sa_in_w  = (const float*)d_in[6];
    const float* sa_in_b  = (const float*)d_in[7];
    const float* sa_out_w = (const float*)d_in[8];
    const float* sa_out_b = (const float*)d_in[9];
    const float* ca_in_w  = (const float*)d_in[10];
    const float* ca_in_b  = (const float*)d_in[11];
    const float* ca_out_w = (const float*)d_in[12];
    const float* ca_out_b = (const float*)d_in[13];
    const float* ln1_g    = (const float*)d_in[14];
    const float* ln1_b    = (const float*)d_in[15];
    const float* ln2_g    = (const float*)d_in[16];
    const float* ln2_b    = (const float*)d_in[17];
    const float* ln3_g    = (const float*)d_in[18];
    const float* ln3_b    = (const float*)d_in[19];
    const float* ff1_w    = (const float*)d_in[20];
    const float* ff1_b    = (const float*)d_in[21];
    const float* ff2_w    = (const float*)d_in[22];
    const float* ff2_b    = (const float*)d_in[23];
    const float* out_w    = (const float*)d_in[24];
    const float* out_b    = (const float*)d_in[25];

    float *m_, *mem_, *x_, *h_, *qkv_, *sc_, *att_, *ff_, *ho_, *pe_, *cT_;
    cudaGetSymbolAddress((void**)&m_,   g_m);
    cudaGetSymbolAddress((void**)&mem_, g_mem);
    cudaGetSymbolAddress((void**)&x_,   g_x);
    cudaGetSymbolAddress((void**)&h_,   g_h);
    cudaGetSymbolAddress((void**)&qkv_, g_qkv);
    cudaGetSymbolAddress((void**)&sc_,  g_scores);
    cudaGetSymbolAddress((void**)&att_, g_att);
    cudaGetSymbolAddress((void**)&ff_,  g_ff);
    cudaGetSymbolAddress((void**)&ho_,  g_head);
    cudaGetSymbolAddress((void**)&pe_,  g_pe);
    cudaGetSymbolAddress((void**)&cT_,  g_convT);

    pe_k<<<TT, 256>>>(pe_);
    convT_k<<<(4 * H * H + 255) / 256, 256>>>(conv_w, cT_);

    // m = memory @ in_w^T + in_b
    gemm2<true, EPI_BIAS, 128><<<gg128(BB * SS, H), 256>>>(
        memory, in_w, in_b, nullptr, m_,
        BB * SS, H, H, H, H, H, Z6, 1, 1.f);

    // conv upsample, all 4 taps in one batched launch (z = tap index)
    gemm2<true, EPI_CONV, 128><<<gg128(BB * SS, H, 4), 256>>>(
        m_, cT_, conv_b, pe_, mem_,
        BB * SS, H, H, H, H, H,
        0L, 0L, 0L, (long)H * H, 0L, 0L, 4, 1.f);

    xinit_k<<<(BB * TT * H + 255) / 256, 256>>>(qemb, pe_, x_);

    const long sQb = (long)TT * 3 * H;
    const long sScb = (long)NHEAD * TT * TT;
    const long sSch = (long)TT * TT;

    for (int l = 0; l < NL; l++) {
        // ======== self-attention ========
        ln_k<<<BB * TT, 128>>>(x_, ln1_g + l * H, ln1_b + l * H, h_);
        gemm2<true, EPI_BIAS, 128><<<gg128(BB * TT, 3 * H), 256>>>(
            h_, sa_in_w + (long)l * 3 * H * H, sa_in_b + (long)l * 3 * H, nullptr, qkv_,
            BB * TT, 3 * H, H, H, H, 3 * H, Z6, 1, 1.f);
        gemm2<true, EPI_SCALE, 128><<<dim3(4, 4, BB * NHEAD), 256>>>(
            qkv_, qkv_ + H, nullptr, nullptr, sc_,
            TT, TT, DHD, 3 * H, 3 * H, TT,
            sQb, (long)DHD, sQb, (long)DHD, sScb, sSch,
            NHEAD, 0.125f);
        softmax_k<<<BB * NHEAD * TT, 128>>>(sc_);
        gemm2<false, EPI_NONE, 64><<<dim3(1, 4, BB * NHEAD), 256>>>(
            sc_, qkv_ + 2 * H, nullptr, nullptr, att_,
            TT, DHD, TT, TT, 3 * H, H,
            sScb, sSch, sQb, (long)DHD, (long)TT * H, (long)DHD,
            NHEAD, 1.f);
        gemm2<true, EPI_BIAS_RES, 128><<<gg128(BB * TT, H), 256>>>(
            att_, sa_out_w + (long)l * H * H, sa_out_b + (long)l * H, x_, x_,
            BB * TT, H, H, H, H, H, Z6, 1, 1.f);

        // ======== cross-attention ========
        ln_k<<<BB * TT, 128>>>(x_, ln2_g + l * H, ln2_b + l * H, h_);
        gemm2<true, EPI_BIAS, 128><<<gg128(BB * TT, H), 256>>>(
            h_, ca_in_w + (long)l * 3 * H * H, ca_in_b + (long)l * 3 * H, nullptr, qkv_,
            BB * TT, H, H, H, H, 3 * H, Z6, 1, 1.f);
        gemm2<true, EPI_BIAS, 128><<<gg128(BB * TT, 2 * H), 256>>>(
            mem_, ca_in_w + (long)l * 3 * H * H + (long)H * H,
            ca_in_b + (long)l * 3 * H + H, nullptr, qkv_ + H,
            BB * TT, 2 * H, H, H, H, 3 * H, Z6, 1, 1.f);
        gemm2<true, EPI_SCALE, 128><<<dim3(4, 4, BB * NHEAD), 256>>>(
            qkv_, qkv_ + H, nullptr, nullptr, sc_,
            TT, TT, DHD, 3 * H, 3 * H, TT,
            sQb, (long)DHD, sQb, (long)DHD, sScb, sSch,
            NHEAD, 0.125f);
        softmax_k<<<BB * NHEAD * TT, 128>>>(sc_);
        gemm2<false, EPI_NONE, 64><<<dim3(1, 4, BB * NHEAD), 256>>>(
            sc_, qkv_ + 2 * H, nullptr, nullptr, att_,
            TT, DHD, TT, TT, 3 * H, H,
            sScb, sSch, sQb, (long)DHD, (long)TT * H, (long)DHD,
            NHEAD, 1.f);
        gemm2<true, EPI_BIAS_RES, 128><<<gg128(BB * TT, H), 256>>>(
            att_, ca_out_w + (long)l * H * H, ca_out_b + (long)l * H, x_, x_,
            BB * TT, H, H, H, H, H, Z6, 1, 1.f);

        // ======== FFN ========
        ln_k<<<BB * TT, 128>>>(x_, ln3_g + l * H, ln3_b + l * H, h_);
        gemm2<true, EPI_BIAS_GELU, 128><<<gg128(BB * TT, FF), 256>>>(
            h_, ff1_w + (long)l * FF * H, ff1_b + (long)l * FF, nullptr, ff_,
            BB * TT, FF, H, H, H, FF, Z6, 1, 1.f);
        gemm2<true, EPI_BIAS_RES, 128><<<gg128(BB * TT, H), 256>>>(
            ff_, ff2_w + (long)l * H * FF, ff2_b + (long)l * H, x_, x_,
            BB * TT, H, FF, FF, FF, H, Z6, 1, 1.f);
    }

    gemm2<true, EPI_BIAS, 128><<<gg128(BB * TT, NOUT), 256>>>(
        x_, out_w, out_b, nullptr, ho_,
        BB * TT, NOUT, H, H, H, NOUT, Z6, 1, 1.f);

    kin_k<<<(BB * TT + 255) / 256, 256>>>(ho_, (float*)d_out);
}

// round 3
// speedup vs baseline: 3.6396x; 2.5488x over previous
#include <cuda_runtime.h>
#include <math.h>
#include <stdint.h>

#define H 512
#define BB 32
#define SS 128
#define TT 512
#define NHEAD 8
#define DHD 64
#define NL 4
#define FF 2048
#define NOUT 102
#define NJ 50

// ---------------- scratch ----------------
__device__ float g_m[BB * SS * H];
__device__ float g_mem[BB * TT * H];
__device__ float g_x[BB * TT * H];
__device__ float g_h[BB * TT * H];
__device__ float g_qkv[BB * TT * 3 * H];
__device__ float g_scores[BB * NHEAD * TT * TT];
__device__ float g_att[BB * TT * H];
__device__ float g_ff[BB * TT * FF];
__device__ float g_head[BB * TT * NOUT];
__device__ float g_pe[TT * H];
__device__ float g_convT[4 * H * H];

__constant__ int PAR[NJ] = {
    -1, 0, 1, 2, 3, 1, 5, 6, 1,
    4, 9, 10, 11,  4, 13, 14, 15,  4, 17, 18, 19,  4, 21, 22, 23,  4, 25, 26, 27,
    7, 29, 30, 31, 7, 33, 34, 35,  7, 37, 38, 39,  7, 41, 42, 43,  7, 45, 46, 47,
    8
};

#define EPI_NONE 0
#define EPI_SCALE 1
#define EPI_BIAS 2
#define EPI_BIAS_RES 3
#define EPI_BIAS_GELU 4
#define EPI_CONV 5

// ---------------- ptx helpers ----------------
__device__ __forceinline__ uint32_t f2tf(float f)
{
    uint32_t u;
    asm("cvt.rna.tf32.f32 %0, %1;" : "=r"(u) : "f"(f));
    return u;
}
__device__ __forceinline__ void cp16(uint32_t dst, const void* src)
{
    asm volatile("cp.async.cg.shared.global [%0], [%1], 16;\n" :: "r"(dst), "l"(src));
}
__device__ __forceinline__ void cp16z(uint32_t dst, const void* src, bool p)
{
    int sz = p ? 16 : 0;
    asm volatile("cp.async.cg.shared.global [%0], [%1], 16, %2;\n"
                 :: "r"(dst), "l"(src), "r"(sz));
}
__device__ __forceinline__ void cpcommit()
{
    asm volatile("cp.async.commit_group;\n" ::: "memory");
}
template <int W>
__device__ __forceinline__ void cpwait()
{
    asm volatile("cp.async.wait_group %0;\n" :: "n"(W) : "memory");
}
__device__ __forceinline__ void mma8(float* d, const uint32_t* a, const uint32_t* b)
{
    asm volatile(
        "mma.sync.aligned.m16n8k8.row.col.f32.tf32.tf32.f32 "
        "{%0,%1,%2,%3}, {%4,%5,%6,%7}, {%8,%9}, {%0,%1,%2,%3};\n"
        : "+f"(d[0]), "+f"(d[1]), "+f"(d[2]), "+f"(d[3])
        : "r"(a[0]), "r"(a[1]), "r"(a[2]), "r"(a[3]), "r"(b[0]), "r"(b[1]));
}

// ---------------- tf32 tensor-core GEMM ----------------
// C[r,c] = sum_k A[r,k] * (TRANSB ? B[c,k] : B[k,c])  per batch z.
// Constraints used here: M % 128 == 0, K % 32 == 0, rows 16B-aligned.
template <bool TRANSB, int EPI, int BN_>
__global__ void __launch_bounds__(256, 2) gemm3(
    const float* __restrict__ A, const float* __restrict__ Bm,
    const float* __restrict__ bias, const float* __restrict__ resid,
    float* __restrict__ C,
    int M, int N, int K, int lda, int ldb, int ldc,
    long sAb, long sAh, long sBb, long sBh, long sCb, long sCh,
    int nh, float scale)
{
    constexpr int BM = 128, BK = 32;
    constexpr int WGN = 4;               // warps along n
    constexpr int WTM = 64, WTN = BN_ / WGN;  // warp tile
    constexpr int MT = WTM / 16;         // 4
    constexpr int NT = WTN / 8;          // 4 (BN=128) or 2 (BN=64)
    constexpr int LDA = BK + 4;          // 36 floats
    constexpr int LDB = TRANSB ? (BK + 4) : (BN_ + 4);
    constexpr int SBR = TRANSB ? BN_ : BK;
    constexpr int ACH = BM * BK / 4 / 256;        // A float4 chunks per thread (4)
    constexpr int BCH = SBR * (TRANSB ? BK : BN_) / 4 / 256;

    extern __shared__ float sm[];
    float* sA = sm;                       // [2][BM][LDA]
    float* sB = sm + 2 * BM * LDA;        // [2][SBR][LDB]
    const uint32_t sAu = (uint32_t)__cvta_generic_to_shared(sA);
    const uint32_t sBu = (uint32_t)__cvta_generic_to_shared(sB);

    const int z = blockIdx.z;
    const int bb = z / nh, hh = z - bb * nh;
    A += (long)bb * sAb + (long)hh * sAh;
    Bm += (long)bb * sBb + (long)hh * sBh;
    const long coff = (long)bb * sCb + (long)hh * sCh;

    const int row0 = blockIdx.y * BM;
    const int col0 = blockIdx.x * BN_;
    const int tid = threadIdx.x;
    const int warp = tid >> 5;
    const int lane = tid & 31;
    const int wm = warp >> 2;            // 0..1
    const int wn = warp & 3;             // 0..3
    const int gid = lane >> 2;           // 0..7
    const int tig = lane & 3;            // 0..3

    float acc[MT][NT][4];
#pragma unroll
    for (int i = 0; i < MT; i++)
#pragma unroll
        for (int j = 0; j < NT; j++)
#pragma unroll
            for (int q = 0; q < 4; q++) acc[i][j][q] = 0.f;

    auto cpA = [&](int k0, int st) {
#pragma unroll
        for (int l = 0; l < ACH; l++) {
            int idx = l * 256 + tid;
            int r = idx >> 3;
            int cq = (idx & 7) * 4;
            cp16(sAu + (uint32_t)(st * BM * LDA + r * LDA + cq) * 4,
                 A + (long)(row0 + r) * lda + k0 + cq);
        }
    };
    auto cpB = [&](int k0, int st) {
        if (TRANSB) {
#pragma unroll
            for (int l = 0; l < BCH; l++) {
                int idx = l * 256 + tid;
                int n = idx >> 3;
                int cq = (idx & 7) * 4;
                cp16z(sBu + (uint32_t)(st * SBR * LDB + n * LDB + cq) * 4,
                      Bm + (long)(col0 + n) * ldb + k0 + cq,
                      (col0 + n) < N);
            }
        } else {
#pragma unroll
            for (int l = 0; l < BCH; l++) {
                int idx = l * 256 + tid;
                int kk = idx / (BN_ / 4);
                int nq = (idx % (BN_ / 4)) * 4;
                cp16(sBu + (uint32_t)(st * SBR * LDB + kk * LDB + nq) * 4,
                     Bm + (long)(k0 + kk) * ldb + col0 + nq);
            }
        }
    };

    auto compute = [&](int st) {
        const float* pA = sA + st * BM * LDA;
        const float* pB = sB + st * SBR * LDB;
#pragma unroll
        for (int ks = 0; ks < 4; ks++) {
            const int k = ks * 8;
            uint32_t af[MT][4], bf[NT][2];
#pragma unroll
            for (int mi = 0; mi < MT; mi++) {
                int r0 = wm * WTM + mi * 16 + gid;
                af[mi][0] = f2tf(pA[r0 * LDA + k + tig]);
                af[mi][1] = f2tf(pA[(r0 + 8) * LDA + k + tig]);
                af[mi][2] = f2tf(pA[r0 * LDA + k + tig + 4]);
                af[mi][3] = f2tf(pA[(r0 + 8) * LDA + k + tig + 4]);
            }
#pragma unroll
            for (int ni = 0; ni < NT; ni++) {
                int n0 = wn * WTN + ni * 8 + gid;
                if (TRANSB) {
                    bf[ni][0] = f2tf(pB[n0 * LDB + k + tig]);
                    bf[ni][1] = f2tf(pB[n0 * LDB + k + tig + 4]);
                } else {
                    bf[ni][0] = f2tf(pB[(k + tig) * LDB + n0]);
                    bf[ni][1] = f2tf(pB[(k + tig + 4) * LDB + n0]);
                }
            }
#pragma unroll
            for (int mi = 0; mi < MT; mi++)
#pragma unroll
                for (int ni = 0; ni < NT; ni++)
                    mma8(acc[mi][ni], af[mi], bf[ni]);
        }
    };

    const int nt = K / BK;
    cpA(0, 0); cpB(0, 0); cpcommit();
    if (nt > 1) { cpA(BK, 1); cpB(BK, 1); cpcommit(); }

    for (int t = 0; t < nt; t++) {
        if (t < nt - 1) cpwait<1>(); else cpwait<0>();
        __syncthreads();
        compute(t & 1);
        __syncthreads();
        if (t + 2 < nt) { cpA((t + 2) * BK, t & 1); cpB((t + 2) * BK, t & 1); cpcommit(); }
    }

    // ---- epilogue ----
    auto emit = [&](int r, int c, float v) {
        if (EPI == EPI_SCALE) v *= scale;
        if (EPI == EPI_BIAS || EPI == EPI_BIAS_RES || EPI == EPI_BIAS_GELU || EPI == EPI_CONV)
            v += bias[c];
        if (EPI == EPI_BIAS_GELU)
            v = 0.5f * v * (1.f + erff(v * 0.70710678118654752f));
        if (EPI == EPI_CONV) {
            int b_ = r >> 7;
            int s_ = r & 127;
            int t_ = s_ * 4 + hh;
            C[((long)b_ * TT + t_) * ldc + c] = v + resid[t_ * H + c];
        } else {
            long idx = coff + (long)r * ldc + c;
            if (EPI == EPI_BIAS_RES) v += resid[idx];
            C[idx] = v;
        }
    };

#pragma unroll
    for (int mi = 0; mi < MT; mi++) {
        int r0 = row0 + wm * WTM + mi * 16 + gid;
#pragma unroll
        for (int ni = 0; ni < NT; ni++) {
            int c0 = col0 + wn * WTN + ni * 8 + tig * 2;
            if (c0 < N)     emit(r0,     c0,     acc[mi][ni][0]);
            if (c0 + 1 < N) emit(r0,     c0 + 1, acc[mi][ni][1]);
            if (c0 < N)     emit(r0 + 8, c0,     acc[mi][ni][2]);
            if (c0 + 1 < N) emit(r0 + 8, c0 + 1, acc[mi][ni][3]);
        }
    }
}

// ---------------- LayerNorm ----------------
__global__ void ln_k(const float* __restrict__ x, const float* __restrict__ g,
                     const float* __restrict__ b, float* __restrict__ o)
{
    long row = blockIdx.x;
    int t = threadIdx.x;
    float4 v = ((const float4*)(x + row * H))[t];
    float s = v.x + v.y + v.z + v.w;
    float ss = v.x * v.x + v.y * v.y + v.z * v.z + v.w * v.w;
#pragma unroll
    for (int off = 16; off; off >>= 1) {
        s += __shfl_xor_sync(0xffffffffu, s, off);
        ss += __shfl_xor_sync(0xffffffffu, ss, off);
    }
    __shared__ float sm0[4], sm1[4];
    int w = t >> 5;
    if ((t & 31) == 0) { sm0[w] = s; sm1[w] = ss; }
    __syncthreads();
    s = sm0[0] + sm0[1] + sm0[2] + sm0[3];
    ss = sm1[0] + sm1[1] + sm1[2] + sm1[3];
    float mean = s * (1.f / H);
    float var = ss * (1.f / H) - mean * mean;
    float rstd = rsqrtf(var + 1e-5f);
    float4 gg = ((const float4*)g)[t];
    float4 bb4 = ((const float4*)b)[t];
    float4 out;
    out.x = (v.x - mean) * rstd * gg.x + bb4.x;
    out.y = (v.y - mean) * rstd * gg.y + bb4.y;
    out.z = (v.z - mean) * rstd * gg.z + bb4.z;
    out.w = (v.w - mean) * rstd * gg.w + bb4.w;
    ((float4*)(o + row * H))[t] = out;
}

// ---------------- softmax ----------------
__global__ void softmax_k(float* __restrict__ sc)
{
    long row = blockIdx.x;
    int t = threadIdx.x;
    float4* p = (float4*)(sc + row * 512);
    float4 v = p[t];
    float mx = fmaxf(fmaxf(v.x, v.y), fmaxf(v.z, v.w));
#pragma unroll
    for (int off = 16; off; off >>= 1) mx = fmaxf(mx, __shfl_xor_sync(0xffffffffu, mx, off));
    __shared__ float sm0[4], sm1[4];
    int w = t >> 5;
    if ((t & 31) == 0) sm0[w] = mx;
    __syncthreads();
    mx = fmaxf(fmaxf(sm0[0], sm0[1]), fmaxf(sm0[2], sm0[3]));
    v.x = expf(v.x - mx); v.y = expf(v.y - mx);
    v.z = expf(v.z - mx); v.w = expf(v.w - mx);
    float s = v.x + v.y + v.z + v.w;
#pragma unroll
    for (int off = 16; off; off >>= 1) s += __shfl_xor_sync(0xffffffffu, s, off);
    if ((t & 31) == 0) sm1[w] = s;
    __syncthreads();
    s = sm1[0] + sm1[1] + sm1[2] + sm1[3];
    float inv = 1.f / s;
    v.x *= inv; v.y *= inv; v.z *= inv; v.w *= inv;
    p[t] = v;
}

// ---------------- misc kernels ----------------
__global__ void pe_k(float* __restrict__ pe)
{
    int t = blockIdx.x;
    int i = threadIdx.x;
    float div = expf(-(float)(2 * i) * (logf(10000.f) / (float)H));
    float a = (float)t * div;
    pe[t * H + 2 * i] = sinf(a);
    pe[t * H + 2 * i + 1] = cosf(a);
}

__global__ void convT_k(const float* __restrict__ w, float* __restrict__ o)
{
    int idx = blockIdx.x * blockDim.x + threadIdx.x;
    if (idx >= 4 * H * H) return;
    int k = idx / (H * H);
    int d = (idx / H) % H;
    int c = idx % H;
    o[idx] = w[c * H * 4 + d * 4 + k];
}

__global__ void xinit_k(const float* __restrict__ qe, const float* __restrict__ pe,
                        float* __restrict__ x)
{
    long i = blockIdx.x * (long)blockDim.x + threadIdx.x;
    if (i >= (long)BB * TT * H) return;
    int td = (int)(i % (TT * H));
    x[i] = qe[td] + pe[td];
}

__global__ void kin_k(const float* __restrict__ ho, float* __restrict__ out)
{
    int row = blockIdx.x * blockDim.x + threadIdx.x;
    if (row >= BB * TT) return;
    const float* r = ho + (long)row * NOUT;
    float* o = out + (long)row * (3 * NJ);
    float gx[NJ], px[NJ], py[NJ];
    gx[0] = 0.f;
    px[0] = r[100];
    py[0] = r[101];
    o[0] = px[0]; o[1] = py[0]; o[2] = 1.f;
    for (int j = 1; j < NJ; j++) {
        int pa = PAR[j];
        float gg = gx[pa] + r[j];
        gx[j] = gg;
        float s = r[50 + j];
        float sn, cs;
        sincosf(gg, &sn, &cs);
        px[j] = px[pa] + cs * s;
        py[j] = py[pa] + sn * s;
        o[j * 3 + 0] = px[j];
        o[j * 3 + 1] = py[j];
        o[j * 3 + 2] = 1.f;
    }
}

// ---------------- launcher ----------------
static inline dim3 gg128(int M, int N, int bz = 1)
{
    return dim3((N + 127) / 128, (M + 127) / 128, bz);
}

#define Z6 0L, 0L, 0L, 0L, 0L, 0L

// smem bytes: (2*128*36 + 2*SBR*LDB) * 4
#define SMEM_T128 73728   // TRANSB, BN=128: (9216 + 9216)*4
#define SMEM_N64  54272   // nonTRANS, BN=64: (9216 + 4352)*4

extern "C" void kernel_launch(void* const* d_in, const int* in_sizes, int n_in,
                              void* d_out, int out_size)
{
    const float* memory   = (const float*)d_in[0];
    const float* in_w     = (const float*)d_in[1];
    const float* in_b     = (const float*)d_in[2];
    const float* conv_w   = (const float*)d_in[3];
    const float* conv_b   = (const float*)d_in[4];
    const float* qemb     = (const float*)d_in[5];
    const float* sa_in_w  = (const float*)d_in[6];
    const float* sa_in_b  = (const float*)d_in[7];
    const float* sa_out_w = (const float*)d_in[8];
    const float* sa_out_b = (const float*)d_in[9];
    const float* ca_in_w  = (const float*)d_in[10];
    const float* ca_in_b  = (const float*)d_in[11];
    const float* ca_out_w = (const float*)d_in[12];
    const float* ca_out_b = (const float*)d_in[13];
    const float* ln1_g    = (const float*)d_in[14];
    const float* ln1_b    = (const float*)d_in[15];
    const float* ln2_g    = (const float*)d_in[16];
    const float* ln2_b    = (const float*)d_in[17];
    const float* ln3_g    = (const float*)d_in[18];
    const float* ln3_b    = (const float*)d_in[19];
    const float* ff1_w    = (const float*)d_in[20];
    const float* ff1_b    = (const float*)d_in[21];
    const float* ff2_w    = (const float*)d_in[22];
    const float* ff2_b    = (const float*)d_in[23];
    const float* out_w    = (const float*)d_in[24];
    const float* out_b    = (const float*)d_in[25];

    float *m_, *mem_, *x_, *h_, *qkv_, *sc_, *att_, *ff_, *ho_, *pe_, *cT_;
    cudaGetSymbolAddress((void**)&m_,   g_m);
    cudaGetSymbolAddress((void**)&mem_, g_mem);
    cudaGetSymbolAddress((void**)&x_,   g_x);
    cudaGetSymbolAddress((void**)&h_,   g_h);
    cudaGetSymbolAddress((void**)&qkv_, g_qkv);
    cudaGetSymbolAddress((void**)&sc_,  g_scores);
    cudaGetSymbolAddress((void**)&att_, g_att);
    cudaGetSymbolAddress((void**)&ff_,  g_ff);
    cudaGetSymbolAddress((void**)&ho_,  g_head);
    cudaGetSymbolAddress((void**)&pe_,  g_pe);
    cudaGetSymbolAddress((void**)&cT_,  g_convT);

    // opt-in large dynamic smem (idempotent; not a stream op — capture-safe)
    cudaFuncSetAttribute(gemm3<true,  EPI_BIAS,      128>, cudaFuncAttributeMaxDynamicSharedMemorySize, SMEM_T128);
    cudaFuncSetAttribute(gemm3<true,  EPI_CONV,      128>, cudaFuncAttributeMaxDynamicSharedMemorySize, SMEM_T128);
    cudaFuncSetAttribute(gemm3<true,  EPI_SCALE,     128>, cudaFuncAttributeMaxDynamicSharedMemorySize, SMEM_T128);
    cudaFuncSetAttribute(gemm3<true,  EPI_BIAS_RES,  128>, cudaFuncAttributeMaxDynamicSharedMemorySize, SMEM_T128);
    cudaFuncSetAttribute(gemm3<true,  EPI_BIAS_GELU, 128>, cudaFuncAttributeMaxDynamicSharedMemorySize, SMEM_T128);
    cudaFuncSetAttribute(gemm3<false, EPI_NONE,       64>, cudaFuncAttributeMaxDynamicSharedMemorySize, SMEM_N64);

    pe_k<<<TT, 256>>>(pe_);
    convT_k<<<(4 * H * H + 255) / 256, 256>>>(conv_w, cT_);

    // m = memory @ in_w^T + in_b
    gemm3<true, EPI_BIAS, 128><<<gg128(BB * SS, H), 256, SMEM_T128>>>(
        memory, in_w, in_b, nullptr, m_,
        BB * SS, H, H, H, H, H, Z6, 1, 1.f);

    // conv upsample (4 taps batched over z)
    gemm3<true, EPI_CONV, 128><<<gg128(BB * SS, H, 4), 256, SMEM_T128>>>(
        m_, cT_, conv_b, pe_, mem_,
        BB * SS, H, H, H, H, H,
        0L, 0L, 0L, (long)H * H, 0L, 0L, 4, 1.f);

    xinit_k<<<(BB * TT * H + 255) / 256, 256>>>(qemb, pe_, x_);

    const long sQb = (long)TT * 3 * H;
    const long sScb = (long)NHEAD * TT * TT;
    const long sSch = (long)TT * TT;

    for (int l = 0; l < NL; l++) {
        // ======== self-attention ========
        ln_k<<<BB * TT, 128>>>(x_, ln1_g + l * H, ln1_b + l * H, h_);
        gemm3<true, EPI_BIAS, 128><<<gg128(BB * TT, 3 * H), 256, SMEM_T128>>>(
            h_, sa_in_w + (long)l * 3 * H * H, sa_in_b + (long)l * 3 * H, nullptr, qkv_,
            BB * TT, 3 * H, H, H, H, 3 * H, Z6, 1, 1.f);
        gemm3<true, EPI_SCALE, 128><<<dim3(4, 4, BB * NHEAD), 256, SMEM_T128>>>(
            qkv_, qkv_ + H, nullptr, nullptr, sc_,
            TT, TT, DHD, 3 * H, 3 * H, TT,
            sQb, (long)DHD, sQb, (long)DHD, sScb, sSch,
            NHEAD, 0.125f);
        softmax_k<<<BB * NHEAD * TT, 128>>>(sc_);
        gemm3<false, EPI_NONE, 64><<<dim3(1, 4, BB * NHEAD), 256, SMEM_N64>>>(
            sc_, qkv_ + 2 * H, nullptr, nullptr, att_,
            TT, DHD, TT, TT, 3 * H, H,
            sScb, sSch, sQb, (long)DHD, (long)TT * H, (long)DHD,
            NHEAD, 1.f);
        gemm3<true, EPI_BIAS_RES, 128><<<gg128(BB * TT, H), 256, SMEM_T128>>>(
            att_, sa_out_w + (long)l * H * H, sa_out_b + (long)l * H, x_, x_,
            BB * TT, H, H, H, H, H, Z6, 1, 1.f);

        // ======== cross-attention ========
        ln_k<<<BB * TT, 128>>>(x_, ln2_g + l * H, ln2_b + l * H, h_);
        gemm3<true, EPI_BIAS, 128><<<gg128(BB * TT, H), 256, SMEM_T128>>>(
            h_, ca_in_w + (long)l * 3 * H * H, ca_in_b + (long)l * 3 * H, nullptr, qkv_,
            BB * TT, H, H, H, H, 3 * H, Z6, 1, 1.f);
        gemm3<true, EPI_BIAS, 128><<<gg128(BB * TT, 2 * H), 256, SMEM_T128>>>(
            mem_, ca_in_w + (long)l * 3 * H * H + (long)H * H,
            ca_in_b + (long)l * 3 * H + H, nullptr, qkv_ + H,
            BB * TT, 2 * H, H, H, H, 3 * H, Z6, 1, 1.f);
        gemm3<true, EPI_SCALE, 128><<<dim3(4, 4, BB * NHEAD), 256, SMEM_T128>>>(
            qkv_, qkv_ + H, nullptr, nullptr, sc_,
            TT, TT, DHD, 3 * H, 3 * H, TT,
            sQb, (long)DHD, sQb, (long)DHD, sScb, sSch,
            NHEAD, 0.125f);
        softmax_k<<<BB * NHEAD * TT, 128>>>(sc_);
        gemm3<false, EPI_NONE, 64><<<dim3(1, 4, BB * NHEAD), 256, SMEM_N64>>>(
            sc_, qkv_ + 2 * H, nullptr, nullptr, att_,
            TT, DHD, TT, TT, 3 * H, H,
            sScb, sSch, sQb, (long)DHD, (long)TT * H, (long)DHD,
            NHEAD, 1.f);
        gemm3<true, EPI_BIAS_RES, 128><<<gg128(BB * TT, H), 256, SMEM_T128>>>(
            att_, ca_out_w + (long)l * H * H, ca_out_b + (long)l * H, x_, x_,
            BB * TT, H, H, H, H, H, Z6, 1, 1.f);

        // ======== FFN ========
        ln_k<<<BB * TT, 128>>>(x_, ln3_g + l * H, ln3_b + l * H, h_);
        gemm3<true, EPI_BIAS_GELU, 128><<<gg128(BB * TT, FF), 256, SMEM_T128>>>(
            h_, ff1_w + (long)l * FF * H, ff1_b + (long)l * FF, nullptr, ff_,
            BB * TT, FF, H, H, H, FF, Z6, 1, 1.f);
        gemm3<true, EPI_BIAS_RES, 128><<<gg128(BB * TT, H), 256, SMEM_T128>>>(
            ff_, ff2_w + (long)l * H * FF, ff2_b + (long)l * H, x_, x_,
            BB * TT, H, FF, FF, FF, H, Z6, 1, 1.f);
    }

    gemm3<true, EPI_BIAS, 128><<<gg128(BB * TT, NOUT), 256, SMEM_T128>>>(
        x_, out_w, out_b, nullptr, ho_,
        BB * TT, NOUT, H, H, H, NOUT, Z6, 1, 1.f);

    kin_k<<<(BB * TT + 255) / 256, 256>>>(ho_, (float*)d_out);
}